// round 5
// baseline (speedup 1.0000x reference)
#include <cuda_runtime.h>
#include <math.h>

#define NW 22

// R5: same factored math, but outputs staged in SMEM and drained via
// cp.async.bulk (TMA store) to bypass the per-thread STG path.
//
//   out[4b+2i+j] = |TA[(b>>9)&1023] * TB[b&1023]| * S[c19,c0,c1,i,j]
//   b = (blk<<13) + (kk<<10) + t ; kk = tile 0..7, t = 0..1023
//   B-index = t (k-invariant), sS-index from bits 0,18,19 (k-invariant),
//   A-index = ((blk<<4)|(kk<<1)|(t>>9)) & 1023 (warp-uniform).

__device__ __forceinline__ unsigned smem_u32(const void* p) {
    return (unsigned)__cvta_generic_to_shared(p);
}

__global__ void __launch_bounds__(1024) qk_fused(const float* __restrict__ x,
                                                 const float* __restrict__ y,
                                                 float4* __restrict__ out) {
    __shared__ float cx[NW], sx[NW], cy[NW], sy[NW];
    __shared__ float pc[NW], ps[NW];
    __shared__ float sTA[1024], sTB[1024];
    __shared__ float4 sS[8];
    __shared__ __align__(16) float4 sBuf[2][1024];   // 2 x 16KB staging tiles
    const int t = threadIdx.x;

    if (t < NW) {
        float sxx, cxx, syy, cyy;
        __sincosf(0.5f * x[t], &sxx, &cxx);
        __sincosf(0.5f * y[t], &syy, &cyy);
        cx[t] = cxx; sx[t] = sxx; cy[t] = cyy; sy[t] = syy;
        pc[t] = cxx * cyy; ps[t] = sxx * syy;
    }
    __syncthreads();

    // One TA and one TB entry per thread.
    {
        int u = t ^ (t >> 1);
        float a = 1.0f, bb = 1.0f;
        #pragma unroll
        for (int j = 0; j < 9; ++j) {
            bool bit = (u >> j) & 1;
            a  *= bit ? ps[10 - j] : pc[10 - j];   // wires 2..10
            bb *= bit ? ps[19 - j] : pc[19 - j];   // wires 11..19
        }
        sTA[t] = a;
        sTB[t] = bb;
    }

    // S table: pre-contracted 2x2 matmul tail + abs (32 scalars).
    if (t < 32) {
        int j   =  t        & 1;
        int i   = (t >> 1)  & 1;
        int c1  = (t >> 2)  & 1;
        int c0  = (t >> 3)  & 1;
        int c19 = (t >> 4)  & 1;
        float s = 0.0f;
        #pragma unroll
        for (int k = 0; k < 2; ++k) {
            float ty = ((c19 ^ i)     ? sy[20] : cy[20])
                     * ((i   ^ k)     ? sy[21] : cy[21])
                     * ((c0  ^ k)     ? sy[0]  : cy[0])
                     * ((c0 ^ c1 ^ k) ? sy[1]  : cy[1]);
            float tx = ((c19 ^ k)     ? sx[20] : cx[20])
                     * ((k   ^ j)     ? sx[21] : cx[21])
                     * ((c0  ^ j)     ? sx[0]  : cx[0])
                     * ((c0 ^ c1 ^ j) ? sx[1]  : cx[1]);
            s += ty * tx;
        }
        reinterpret_cast<float*>(sS)[t] = fabsf(s);
    }
    __syncthreads();

    const unsigned base = (unsigned)blockIdx.x << 13;
    const unsigned b0 = base + (unsigned)t;
    const float B = sTB[t];
    const float4 s = sS[((b0 & 1u) << 2) | (((b0 >> 19) & 1u) << 1)
                        | ((b0 >> 18) & 1u)];
    const float Bsx = B * s.x, Bsy = B * s.y, Bsz = B * s.z, Bsw = B * s.w;

    #pragma unroll
    for (int kk = 0; kk < 8; ++kk) {
        const int buf = kk & 1;
        // Reuse guard: allow at most 1 bulk group still reading SMEM.
        if (kk >= 2 && t == 0) {
            asm volatile("cp.async.bulk.wait_group.read 1;" ::: "memory");
        }
        __syncthreads();

        unsigned b = b0 + ((unsigned)kk << 10);
        float A = fabsf(sTA[(b >> 9) & 1023u]);     // warp-uniform LDS
        float4 o;
        o.x = fabsf(A * Bsx);
        o.y = fabsf(A * Bsy);
        o.z = fabsf(A * Bsz);
        o.w = fabsf(A * Bsw);
        sBuf[buf][t] = o;                            // STS.128
        __syncthreads();

        if (t == 0) {
            asm volatile("fence.proxy.async.shared::cta;" ::: "memory");
            unsigned long long dst = (unsigned long long)(out + base + ((unsigned)kk << 10));
            unsigned src = smem_u32(&sBuf[buf][0]);
            asm volatile(
                "cp.async.bulk.global.shared::cta.bulk_group [%0], [%1], %2;"
                :: "l"(dst), "r"(src), "n"(16384) : "memory");
            asm volatile("cp.async.bulk.commit_group;" ::: "memory");
        }
    }

    // Drain all outstanding bulk stores before the block exits (SMEM reuse safety).
    if (t == 0) {
        asm volatile("cp.async.bulk.wait_group 0;" ::: "memory");
    }
    __syncthreads();
}

extern "C" void kernel_launch(void* const* d_in, const int* in_sizes, int n_in,
                              void* d_out, int out_size) {
    const float* x = (const float*)d_in[0];
    const float* y = (const float*)d_in[1];
    // 2^20 float4 outputs / (1024 threads * 8 tiles) = 128 blocks
    qk_fused<<<128, 1024>>>(x, y, (float4*)d_out);
}